// round 1
// baseline (speedup 1.0000x reference)
#include <cuda_runtime.h>
#include <math.h>

#define RB 8
#define NN 128
#define DD 512
#define HH 256
#define KK 64

// Deterministic scratch (no device-side allocation allowed)
__device__ float g_lacc[RB * NN * NN];   // per-r raw logit sums (pre-mean)
__device__ float g_probs[NN * NN];       // sigmoid(logits)*mask, consumed by topk
__device__ int   g_topk[KK];
__device__ float g_pf[KK * DD];          // gathered averaged pair features

// ---------------------------------------------------------------------------
// K1: for one (i, r): X[j,d] = obj[r,i,d]*obj[r,j,d] + geo[r,i,j,d]
//     C = X @ w1a  (128x256, K=512), then logit[j] = sum_h relu(C+b1a)*w2a
//     Write per-r partials to g_lacc (deterministic, no atomics).
// ---------------------------------------------------------------------------
__global__ __launch_bounds__(256, 1)
void k1_o2o(const float* __restrict__ obj, const float* __restrict__ geo,
            const float* __restrict__ w1a, const float* __restrict__ b1a,
            const float* __restrict__ w2a)
{
    __shared__ float As[16][128];   // X chunk, [k][j]
    __shared__ float Bs[16][256];   // w1a chunk, [k][h]

    const int bx = blockIdx.x;      // 0..1023
    const int i  = bx >> 3;
    const int r  = bx & 7;
    const int t  = threadIdx.x;
    const int tx = t & 15;          // h-group: h = tx*16 + hh
    const int ty = t >> 4;          // j-group: j = ty*8 + jj

    const float* obj_r  = obj + r * NN * DD;
    const float* obj_i  = obj_r + i * DD;
    const float* geo_ri = geo + (size_t)(r * NN + i) * (size_t)(NN * DD);

    float acc[8][16];
#pragma unroll
    for (int a = 0; a < 8; a++)
#pragma unroll
        for (int b = 0; b < 16; b++) acc[a][b] = 0.f;

    for (int d0 = 0; d0 < DD; d0 += 16) {
        // Build X tile on the fly: 128 rows x 16 k, stored transposed [k][j]
#pragma unroll
        for (int l = 0; l < 2; l++) {
            int q  = t + l * 256;         // 0..511
            int j  = q >> 2;
            int kq = (q & 3) << 2;
            float4 g4 = *(const float4*)(geo_ri + j * DD + d0 + kq);
            float4 oj = *(const float4*)(obj_r  + j * DD + d0 + kq);
            float4 oi = *(const float4*)(obj_i  + d0 + kq);   // broadcast, L1 hit
            As[kq + 0][j] = fmaf(oi.x, oj.x, g4.x);
            As[kq + 1][j] = fmaf(oi.y, oj.y, g4.y);
            As[kq + 2][j] = fmaf(oi.z, oj.z, g4.z);
            As[kq + 3][j] = fmaf(oi.w, oj.w, g4.w);
        }
        // w1a chunk [16][256]
#pragma unroll
        for (int l = 0; l < 4; l++) {
            int q  = t + l * 256;         // 0..1023
            int k  = q >> 6;
            int h4 = (q & 63) << 2;
            *(float4*)&Bs[k][h4] = *(const float4*)(w1a + (d0 + k) * HH + h4);
        }
        __syncthreads();

#pragma unroll 4
        for (int k = 0; k < 16; k++) {
            float a[8], b[16];
            *(float4*)&a[0]  = *(const float4*)&As[k][ty * 8];
            *(float4*)&a[4]  = *(const float4*)&As[k][ty * 8 + 4];
            *(float4*)&b[0]  = *(const float4*)&Bs[k][tx * 16];
            *(float4*)&b[4]  = *(const float4*)&Bs[k][tx * 16 + 4];
            *(float4*)&b[8]  = *(const float4*)&Bs[k][tx * 16 + 8];
            *(float4*)&b[12] = *(const float4*)&Bs[k][tx * 16 + 12];
#pragma unroll
            for (int jj = 0; jj < 8; jj++)
#pragma unroll
                for (int hh = 0; hh < 16; hh++)
                    acc[jj][hh] = fmaf(a[jj], b[hh], acc[jj][hh]);
        }
        __syncthreads();
    }

    // Epilogue: partial logit over this thread's 16 h, reduce across tx via smem
    float w2[16], bb[16];
#pragma unroll
    for (int hh = 0; hh < 16; hh++) {
        w2[hh] = w2a[tx * 16 + hh];
        bb[hh] = b1a[tx * 16 + hh];
    }
#pragma unroll
    for (int jj = 0; jj < 8; jj++) {
        float p = 0.f;
#pragma unroll
        for (int hh = 0; hh < 16; hh++)
            p += fmaxf(acc[jj][hh] + bb[hh], 0.f) * w2[hh];
        As[tx][ty * 8 + jj] = p;     // reuse As as reduction buffer
    }
    __syncthreads();
    if (t < 128) {
        float s = 0.f;
#pragma unroll
        for (int x = 0; x < 16; x++) s += As[x][t];
        g_lacc[(r * NN + i) * NN + t] = s;
    }
}

// ---------------------------------------------------------------------------
// K2: reduce the 8 per-r partials (fixed order), mean + b2a -> out o2o;
//     probs = sigmoid * mask
// ---------------------------------------------------------------------------
__global__ void k2_finish(const float* __restrict__ mask,
                          const float* __restrict__ b2a,
                          float* __restrict__ out)
{
    int idx = blockIdx.x * 256 + threadIdx.x;   // 64*256 = 16384
    float s = 0.f;
#pragma unroll
    for (int r = 0; r < RB; r++) s += g_lacc[r * (NN * NN) + idx];
    float v = s * 0.125f + b2a[0];
    out[idx] = v;
    g_probs[idx] = (1.f / (1.f + expf(-v))) * mask[idx];
}

// ---------------------------------------------------------------------------
// K3: top-64 by 64 sequential argmax passes; tie -> lower index (matches
//     jax.lax.top_k stability). Single block, 1024 threads.
// ---------------------------------------------------------------------------
__global__ void k3_topk(float* __restrict__ out)
{
    __shared__ float sv[32];
    __shared__ int   si[32];
    int t = threadIdx.x;

    for (int it = 0; it < KK; it++) {
        float best = -1e30f;
        int   bidx = 0;
        for (int q = t; q < NN * NN; q += 1024) {
            float v = g_probs[q];
            if (v > best || (v == best && q < bidx)) { best = v; bidx = q; }
        }
#pragma unroll
        for (int off = 16; off; off >>= 1) {
            float ov = __shfl_down_sync(0xffffffffu, best, off);
            int   oi = __shfl_down_sync(0xffffffffu, bidx, off);
            if (ov > best || (ov == best && oi < bidx)) { best = ov; bidx = oi; }
        }
        if ((t & 31) == 0) { sv[t >> 5] = best; si[t >> 5] = bidx; }
        __syncthreads();
        if (t < 32) {
            best = sv[t]; bidx = si[t];
#pragma unroll
            for (int off = 16; off; off >>= 1) {
                float ov = __shfl_down_sync(0xffffffffu, best, off);
                int   oi = __shfl_down_sync(0xffffffffu, bidx, off);
                if (ov > best || (ov == best && oi < bidx)) { best = ov; bidx = oi; }
            }
            if (t == 0) {
                g_topk[it] = bidx;
                out[NN * NN + KK * KK + it] = (float)bidx;
                g_probs[bidx] = -1e30f;   // exclude (rewritten by K2 each launch)
            }
        }
        __syncthreads();
    }
}

// ---------------------------------------------------------------------------
// K4: gather averaged pair features only at the 64 selected pairs:
//     pf[p,d] = (1/R) sum_r obj[r,i,d]*obj[r,j,d] + geo[r,i,j,d]
// ---------------------------------------------------------------------------
__global__ void k4_pf(const float* __restrict__ obj, const float* __restrict__ geo)
{
    int p = blockIdx.x;
    int t = threadIdx.x;           // 128 threads, float4 over d
    int ind = g_topk[p];
    int i = ind >> 7;
    int j = ind & 127;
    int d = t * 4;

    float4 s = make_float4(0.f, 0.f, 0.f, 0.f);
#pragma unroll
    for (int r = 0; r < RB; r++) {
        float4 oi = *(const float4*)(obj + (size_t)(r * NN + i) * DD + d);
        float4 oj = *(const float4*)(obj + (size_t)(r * NN + j) * DD + d);
        float4 g  = *(const float4*)(geo + (size_t)((r * NN + i) * NN + j) * DD + d);
        s.x += fmaf(oi.x, oj.x, g.x);
        s.y += fmaf(oi.y, oj.y, g.y);
        s.z += fmaf(oi.z, oj.z, g.z);
        s.w += fmaf(oi.w, oj.w, g.w);
    }
    s.x *= 0.125f; s.y *= 0.125f; s.z *= 0.125f; s.w *= 0.125f;
    *(float4*)(g_pf + p * DD + d) = s;
}

// ---------------------------------------------------------------------------
// K5: p2p scorer. 4096 rows X2[i2*64+j2, d] = pf[i2,d]*pf[j2,d]; fused MLP.
//     256 blocks x 16 rows. Thread map: row = t/16, hgroup = t%16.
// ---------------------------------------------------------------------------
__global__ __launch_bounds__(256, 2)
void k5_p2p(const float* __restrict__ w1b, const float* __restrict__ b1b,
            const float* __restrict__ w2b, const float* __restrict__ b2b,
            float* __restrict__ out)
{
    __shared__ float As2[16][17];   // [k][row], padded vs bank conflicts
    __shared__ float Bs2[16][256];  // w1b chunk

    int t = threadIdx.x;
    int b = blockIdx.x;             // 0..255
    int row0   = b * 16;            // global rows row0..row0+15 (same i2)
    int i2     = row0 >> 6;
    int j2base = row0 & 63;
    int rowl = t >> 4;              // 0..15
    int hg   = t & 15;              // h = hg*16 + hh

    const float* pfi = g_pf + i2 * DD;
    float acc[16];
#pragma unroll
    for (int hh = 0; hh < 16; hh++) acc[hh] = 0.f;

    for (int d0 = 0; d0 < DD; d0 += 16) {
        {
            int rl = t >> 4, k = t & 15;
            As2[k][rl] = pfi[d0 + k] * g_pf[(j2base + rl) * DD + d0 + k];
        }
#pragma unroll
        for (int l = 0; l < 4; l++) {
            int q  = t + l * 256;
            int k  = q >> 6;
            int h4 = (q & 63) << 2;
            *(float4*)&Bs2[k][h4] = *(const float4*)(w1b + (d0 + k) * HH + h4);
        }
        __syncthreads();
#pragma unroll 4
        for (int k = 0; k < 16; k++) {
            float a = As2[k][rowl];
            float bv[16];
            *(float4*)&bv[0]  = *(const float4*)&Bs2[k][hg * 16];
            *(float4*)&bv[4]  = *(const float4*)&Bs2[k][hg * 16 + 4];
            *(float4*)&bv[8]  = *(const float4*)&Bs2[k][hg * 16 + 8];
            *(float4*)&bv[12] = *(const float4*)&Bs2[k][hg * 16 + 12];
#pragma unroll
            for (int hh = 0; hh < 16; hh++)
                acc[hh] = fmaf(a, bv[hh], acc[hh]);
        }
        __syncthreads();
    }

    float p = 0.f;
#pragma unroll
    for (int hh = 0; hh < 16; hh++) {
        int h = hg * 16 + hh;
        p += fmaxf(acc[hh] + b1b[h], 0.f) * w2b[h];
    }
#pragma unroll
    for (int off = 8; off; off >>= 1)
        p += __shfl_xor_sync(0xffffffffu, p, off);   // reduce within 16-lane group
    if (hg == 0)
        out[NN * NN + row0 + rowl] = p + b2b[0];
}

// ---------------------------------------------------------------------------
extern "C" void kernel_launch(void* const* d_in, const int* in_sizes, int n_in,
                              void* d_out, int out_size)
{
    const float* obj  = (const float*)d_in[0];
    const float* geo  = (const float*)d_in[1];
    const float* mask = (const float*)d_in[2];
    const float* w1a  = (const float*)d_in[3];
    const float* b1a  = (const float*)d_in[4];
    const float* w2a  = (const float*)d_in[5];
    const float* b2a  = (const float*)d_in[6];
    const float* w1b  = (const float*)d_in[7];
    const float* b1b  = (const float*)d_in[8];
    const float* w2b  = (const float*)d_in[9];
    const float* b2b  = (const float*)d_in[10];
    float* out = (float*)d_out;

    k1_o2o<<<NN * RB, 256>>>(obj, geo, w1a, b1a, w2a);
    k2_finish<<<64, 256>>>(mask, b2a, out);
    k3_topk<<<1, 1024>>>(out);
    k4_pf<<<KK, 128>>>(obj, geo);
    k5_p2p<<<256, 256>>>(w1b, b1b, w2b, b2b, out);
}

// round 3
// speedup vs baseline: 1.4184x; 1.4184x over previous
#include <cuda_runtime.h>
#include <cstdint>
#include <math.h>

#define RB 8
#define NN 128
#define DD 512
#define HH 256
#define KK 64
#define PAD 20                       // smem row pad (floats): conflict-free for frag patterns

// ---------------------------------------------------------------------------
// Scratch (__device__ globals; no allocation allowed)
// ---------------------------------------------------------------------------
__device__ float g_lacc[RB * NN * NN];
__device__ float g_probs[NN * NN];
__device__ int   g_topk[KK];
__device__ float g_pf[KK * DD];
__device__ float g_wt_hi[HH * DD];   // W^T tf32 hi, [n][k] K-major
__device__ float g_wt_lo[HH * DD];   // residual lo

__device__ __forceinline__ float tf32_rnd(float x) {
    uint32_t r;
    asm("cvt.rna.tf32.f32 %0, %1;" : "=r"(r) : "f"(x));
    return __uint_as_float(r);
}

__device__ __forceinline__ void mma_tf32(float* c, const uint32_t* a, uint32_t b0, uint32_t b1) {
    asm volatile(
        "mma.sync.aligned.m16n8k8.row.col.f32.tf32.tf32.f32 "
        "{%0,%1,%2,%3}, {%4,%5,%6,%7}, {%8,%9}, {%0,%1,%2,%3};"
        : "+f"(c[0]), "+f"(c[1]), "+f"(c[2]), "+f"(c[3])
        : "r"(a[0]), "r"(a[1]), "r"(a[2]), "r"(a[3]), "r"(b0), "r"(b1));
}

// ---------------------------------------------------------------------------
// K0: split & transpose w1a -> Wt_hi/Wt_lo [256][512] K-major, tf32-rounded
// ---------------------------------------------------------------------------
__global__ void k0_split(const float* __restrict__ w1a)
{
    int idx = blockIdx.x * 256 + threadIdx.x;   // 131072
    int k = idx >> 8, n = idx & 255;
    float w  = w1a[idx];                        // w1a[k*256+n]
    float hi = tf32_rnd(w);
    float lo = tf32_rnd(w - hi);
    g_wt_hi[n * DD + k] = hi;
    g_wt_lo[n * DD + k] = lo;
}

// ---------------------------------------------------------------------------
// K1: warp-mma tf32 3x-split GEMM. One (i,r) per CTA, 512 threads (16 warps).
//     Warp (mw, nw): output tile rows mw*32..+31, cols nw*64..+63.
// ---------------------------------------------------------------------------
__global__ __launch_bounds__(512, 1)
void k1_mma(const float* __restrict__ obj, const float* __restrict__ geo,
            const float* __restrict__ b1a, const float* __restrict__ w2a)
{
    extern __shared__ float sm[];
    float* As_hi = sm;                        // [128][PAD]
    float* As_lo = As_hi + 128 * PAD;
    float* Bs_hi = As_lo + 128 * PAD;         // [256][PAD]
    float* Bs_lo = Bs_hi + 256 * PAD;
    float* red   = Bs_lo + 256 * PAD;         // [4][128]
    float* w2s   = red + 512;                 // [256]
    float* b1s   = w2s + 256;                 // [256]

    const int t    = threadIdx.x;
    const int lane = t & 31;
    const int wid  = t >> 5;
    const int mw   = wid & 3;                 // m-tile group
    const int nw   = wid >> 2;                // n-tile group
    const int gr   = lane >> 2;
    const int gc   = lane & 3;
    const int mbase = mw * 32;
    const int nbase = nw * 64;

    const int bx = blockIdx.x;                // 0..1023
    const int i  = bx >> 3;
    const int r  = bx & 7;

    const float* obj_r  = obj + (size_t)r * NN * DD;
    const float* obj_i  = obj_r + (size_t)i * DD;
    const float* geo_ri = geo + ((size_t)(r * NN + i) * NN) * DD;

    if (t < 256) { w2s[t] = w2a[t]; b1s[t] = b1a[t]; }

    float c[2][8][4];
#pragma unroll
    for (int mt = 0; mt < 2; mt++)
#pragma unroll
        for (int nt = 0; nt < 8; nt++)
#pragma unroll
            for (int e = 0; e < 4; e++) c[mt][nt][e] = 0.f;

    const int aj = t >> 2;                    // A-build row
    const int ak = (t & 3) << 2;              // A-build k offset (float4)
    const int bn = t >> 1;                    // B-load row
    const int bk = (t & 1) << 3;              // B-load k offset (two float4)

    for (int kc = 0; kc < DD / 16; kc++) {
        const int k0 = kc * 16;

        // ---- build A chunk (X = oi*oj + geo), hi/lo split ----
        {
            float4 g4 = *(const float4*)(geo_ri + (size_t)aj * DD + k0 + ak);
            float4 oj = *(const float4*)(obj_r  + (size_t)aj * DD + k0 + ak);
            float4 oi = *(const float4*)(obj_i + k0 + ak);
            float4 x, hi, lo;
            x.x = fmaf(oi.x, oj.x, g4.x); x.y = fmaf(oi.y, oj.y, g4.y);
            x.z = fmaf(oi.z, oj.z, g4.z); x.w = fmaf(oi.w, oj.w, g4.w);
            hi.x = tf32_rnd(x.x); hi.y = tf32_rnd(x.y);
            hi.z = tf32_rnd(x.z); hi.w = tf32_rnd(x.w);
            lo.x = tf32_rnd(x.x - hi.x); lo.y = tf32_rnd(x.y - hi.y);
            lo.z = tf32_rnd(x.z - hi.z); lo.w = tf32_rnd(x.w - hi.w);
            *(float4*)(As_hi + aj * PAD + ak) = hi;
            *(float4*)(As_lo + aj * PAD + ak) = lo;
        }
        // ---- load B chunk [256][16] from pre-split global ----
        {
            const float* shi = g_wt_hi + (size_t)bn * DD + k0 + bk;
            const float* slo = g_wt_lo + (size_t)bn * DD + k0 + bk;
            *(float4*)(Bs_hi + bn * PAD + bk)     = *(const float4*)(shi);
            *(float4*)(Bs_hi + bn * PAD + bk + 4) = *(const float4*)(shi + 4);
            *(float4*)(Bs_lo + bn * PAD + bk)     = *(const float4*)(slo);
            *(float4*)(Bs_lo + bn * PAD + bk + 4) = *(const float4*)(slo + 4);
        }
        __syncthreads();

        // ---- two k8 MMA steps ----
#pragma unroll
        for (int ks = 0; ks < 2; ks++) {
            const int kk = ks * 8;
            uint32_t ahi[2][4], alo[2][4];
#pragma unroll
            for (int mt = 0; mt < 2; mt++) {
                int ar = (mbase + mt * 16 + gr) * PAD + kk + gc;
                ahi[mt][0] = __float_as_uint(As_hi[ar]);
                ahi[mt][1] = __float_as_uint(As_hi[ar + 8 * PAD]);
                ahi[mt][2] = __float_as_uint(As_hi[ar + 4]);
                ahi[mt][3] = __float_as_uint(As_hi[ar + 8 * PAD + 4]);
                alo[mt][0] = __float_as_uint(As_lo[ar]);
                alo[mt][1] = __float_as_uint(As_lo[ar + 8 * PAD]);
                alo[mt][2] = __float_as_uint(As_lo[ar + 4]);
                alo[mt][3] = __float_as_uint(As_lo[ar + 8 * PAD + 4]);
            }
#pragma unroll
            for (int nt = 0; nt < 8; nt++) {
                int br = (nbase + nt * 8 + gr) * PAD + kk + gc;
                uint32_t bh0 = __float_as_uint(Bs_hi[br]);
                uint32_t bh1 = __float_as_uint(Bs_hi[br + 4]);
                uint32_t bl0 = __float_as_uint(Bs_lo[br]);
                uint32_t bl1 = __float_as_uint(Bs_lo[br + 4]);
#pragma unroll
                for (int mt = 0; mt < 2; mt++) {
                    mma_tf32(c[mt][nt], ahi[mt], bh0, bh1);
                    mma_tf32(c[mt][nt], ahi[mt], bl0, bl1);
                    mma_tf32(c[mt][nt], alo[mt], bh0, bh1);
                }
            }
        }
        __syncthreads();
    }

    // ---- epilogue: logit[j] = sum_h relu(C + b1a) * w2a ----
    float part[2][2] = {{0.f, 0.f}, {0.f, 0.f}};
#pragma unroll
    for (int mt = 0; mt < 2; mt++)
#pragma unroll
        for (int nt = 0; nt < 8; nt++)
#pragma unroll
            for (int rv = 0; rv < 2; rv++)
#pragma unroll
                for (int e = 0; e < 2; e++) {
                    int h = nbase + nt * 8 + gc * 2 + e;
                    float v = c[mt][nt][rv * 2 + e] + b1s[h];
                    part[mt][rv] += fmaxf(v, 0.f) * w2s[h];
                }
#pragma unroll
    for (int mt = 0; mt < 2; mt++)
#pragma unroll
        for (int rv = 0; rv < 2; rv++) {
            float p = part[mt][rv];
            p += __shfl_xor_sync(0xffffffffu, p, 1);
            p += __shfl_xor_sync(0xffffffffu, p, 2);
            if (gc == 0)
                red[nw * 128 + mbase + mt * 16 + rv * 8 + gr] = p;
        }
    __syncthreads();
    if (t < 128)
        g_lacc[(r * NN + i) * NN + t] =
            (red[t] + red[128 + t]) + (red[256 + t] + red[384 + t]);
}

// ---------------------------------------------------------------------------
// K2: mean over r + b2a -> out; probs = sigmoid*mask
// ---------------------------------------------------------------------------
__global__ void k2_finish(const float* __restrict__ mask,
                          const float* __restrict__ b2a,
                          float* __restrict__ out)
{
    int idx = blockIdx.x * 256 + threadIdx.x;
    float s = 0.f;
#pragma unroll
    for (int r = 0; r < RB; r++) s += g_lacc[r * (NN * NN) + idx];
    float v = s * 0.125f + b2a[0];
    out[idx] = v;
    g_probs[idx] = (1.f / (1.f + expf(-v))) * mask[idx];
}

// ---------------------------------------------------------------------------
// K3: top-64 via 64 argmax passes, tie -> lower index
// ---------------------------------------------------------------------------
__global__ void k3_topk(float* __restrict__ out)
{
    __shared__ float sv[32];
    __shared__ int   si[32];
    int t = threadIdx.x;

    for (int it = 0; it < KK; it++) {
        float best = -1e30f;
        int   bidx = 0;
        for (int q = t; q < NN * NN; q += 1024) {
            float v = g_probs[q];
            if (v > best || (v == best && q < bidx)) { best = v; bidx = q; }
        }
#pragma unroll
        for (int off = 16; off; off >>= 1) {
            float ov = __shfl_down_sync(0xffffffffu, best, off);
            int   oi = __shfl_down_sync(0xffffffffu, bidx, off);
            if (ov > best || (ov == best && oi < bidx)) { best = ov; bidx = oi; }
        }
        if ((t & 31) == 0) { sv[t >> 5] = best; si[t >> 5] = bidx; }
        __syncthreads();
        if (t < 32) {
            best = sv[t]; bidx = si[t];
#pragma unroll
            for (int off = 16; off; off >>= 1) {
                float ov = __shfl_down_sync(0xffffffffu, best, off);
                int   oi = __shfl_down_sync(0xffffffffu, bidx, off);
                if (ov > best || (ov == best && oi < bidx)) { best = ov; bidx = oi; }
            }
            if (t == 0) {
                g_topk[it] = bidx;
                out[NN * NN + KK * KK + it] = (float)bidx;
                g_probs[bidx] = -1e30f;
            }
        }
        __syncthreads();
    }
}

// ---------------------------------------------------------------------------
// K4: gather averaged pair features at top-k pairs
// ---------------------------------------------------------------------------
__global__ void k4_pf(const float* __restrict__ obj, const float* __restrict__ geo)
{
    int p = blockIdx.x;
    int t = threadIdx.x;
    int ind = g_topk[p];
    int i = ind >> 7;
    int j = ind & 127;
    int d = t * 4;

    float4 s = make_float4(0.f, 0.f, 0.f, 0.f);
#pragma unroll
    for (int r = 0; r < RB; r++) {
        float4 oi = *(const float4*)(obj + (size_t)(r * NN + i) * DD + d);
        float4 oj = *(const float4*)(obj + (size_t)(r * NN + j) * DD + d);
        float4 g  = *(const float4*)(geo + (size_t)((r * NN + i) * NN + j) * DD + d);
        s.x += fmaf(oi.x, oj.x, g.x);
        s.y += fmaf(oi.y, oj.y, g.y);
        s.z += fmaf(oi.z, oj.z, g.z);
        s.w += fmaf(oi.w, oj.w, g.w);
    }
    s.x *= 0.125f; s.y *= 0.125f; s.z *= 0.125f; s.w *= 0.125f;
    *(float4*)(g_pf + p * DD + d) = s;
}

// ---------------------------------------------------------------------------
// K5: p2p scorer (fp32, small)
// ---------------------------------------------------------------------------
__global__ __launch_bounds__(256, 2)
void k5_p2p(const float* __restrict__ w1b, const float* __restrict__ b1b,
            const float* __restrict__ w2b, const float* __restrict__ b2b,
            float* __restrict__ out)
{
    __shared__ float As2[16][17];
    __shared__ float Bs2[16][256];

    int t = threadIdx.x;
    int b = blockIdx.x;
    int row0   = b * 16;
    int i2     = row0 >> 6;
    int j2base = row0 & 63;
    int rowl = t >> 4;
    int hg   = t & 15;

    const float* pfi = g_pf + i2 * DD;
    float acc[16];
#pragma unroll
    for (int hh = 0; hh < 16; hh++) acc[hh] = 0.f;

    for (int d0 = 0; d0 < DD; d0 += 16) {
        {
            int rl = t >> 4, k = t & 15;
            As2[k][rl] = pfi[d0 + k] * g_pf[(j2base + rl) * DD + d0 + k];
        }
#pragma unroll
        for (int l = 0; l < 4; l++) {
            int q  = t + l * 256;
            int k  = q >> 6;
            int h4 = (q & 63) << 2;
            *(float4*)&Bs2[k][h4] = *(const float4*)(w1b + (d0 + k) * HH + h4);
        }
        __syncthreads();
#pragma unroll 4
        for (int k = 0; k < 16; k++) {
            float a = As2[k][rowl];
            float bv[16];
            *(float4*)&bv[0]  = *(const float4*)&Bs2[k][hg * 16];
            *(float4*)&bv[4]  = *(const float4*)&Bs2[k][hg * 16 + 4];
            *(float4*)&bv[8]  = *(const float4*)&Bs2[k][hg * 16 + 8];
            *(float4*)&bv[12] = *(const float4*)&Bs2[k][hg * 16 + 12];
#pragma unroll
            for (int hh = 0; hh < 16; hh++)
                acc[hh] = fmaf(a, bv[hh], acc[hh]);
        }
        __syncthreads();
    }

    float p = 0.f;
#pragma unroll
    for (int hh = 0; hh < 16; hh++) {
        int h = hg * 16 + hh;
        p += fmaxf(acc[hh] + b1b[h], 0.f) * w2b[h];
    }
#pragma unroll
    for (int off = 8; off; off >>= 1)
        p += __shfl_xor_sync(0xffffffffu, p, off);
    if (hg == 0)
        out[NN * NN + row0 + rowl] = p + b2b[0];
}

// ---------------------------------------------------------------------------
extern "C" void kernel_launch(void* const* d_in, const int* in_sizes, int n_in,
                              void* d_out, int out_size)
{
    const float* obj  = (const float*)d_in[0];
    const float* geo  = (const float*)d_in[1];
    const float* mask = (const float*)d_in[2];
    const float* w1a  = (const float*)d_in[3];
    const float* b1a  = (const float*)d_in[4];
    const float* w2a  = (const float*)d_in[5];
    const float* b2a  = (const float*)d_in[6];
    const float* w1b  = (const float*)d_in[7];
    const float* b1b  = (const float*)d_in[8];
    const float* w2b  = (const float*)d_in[9];
    const float* b2b  = (const float*)d_in[10];
    float* out = (float*)d_out;

    const int smem_k1 = 16384 * 4;   // 65536 B
    static int smem_set = 0;
    if (!smem_set) {
        cudaFuncSetAttribute(k1_mma, cudaFuncAttributeMaxDynamicSharedMemorySize, smem_k1);
        smem_set = 1;
    }

    k0_split<<<512, 256>>>(w1a);
    k1_mma<<<NN * RB, 512, smem_k1>>>(obj, geo, b1a, w2a);
    k2_finish<<<64, 256>>>(mask, b2a, out);
    k3_topk<<<1, 1024>>>(out);
    k4_pf<<<KK, 128>>>(obj, geo);
    k5_p2p<<<256, 256>>>(w1b, b1b, w2b, b2b, out);
}

// round 4
// speedup vs baseline: 1.8562x; 1.3087x over previous
#include <cuda_runtime.h>
#include <cstdint>
#include <math.h>

#define RB 8
#define NN 128
#define DD 512
#define HH 256
#define KK 64

// ---------------------------------------------------------------------------
// Scratch (__device__ globals; no allocation allowed)
// ---------------------------------------------------------------------------
__device__ float g_lacc[RB * NN * NN];
__device__ float g_probs[NN * NN];
__device__ int   g_topk[KK];
__device__ float g_pf[KK * DD];
__device__ float4 g_wfrag[32 * 2 * 32 * 32];   // [kc][ks][ntg][lane] = (bh0,bh1,bl0,bl1)

__device__ __forceinline__ float tf32_rnd(float x) {
    uint32_t r;
    asm("cvt.rna.tf32.f32 %0, %1;" : "=r"(r) : "f"(x));
    return __uint_as_float(r);
}

__device__ __forceinline__ void mma_tf32(float* c, const uint32_t* a, uint32_t b0, uint32_t b1) {
    asm volatile(
        "mma.sync.aligned.m16n8k8.row.col.f32.tf32.tf32.f32 "
        "{%0,%1,%2,%3}, {%4,%5,%6,%7}, {%8,%9}, {%0,%1,%2,%3};"
        : "+f"(c[0]), "+f"(c[1]), "+f"(c[2]), "+f"(c[3])
        : "r"(a[0]), "r"(a[1]), "r"(a[2]), "r"(a[3]), "r"(b0), "r"(b1));
}

#define CP_ASYNC16(dst_u32, src_ptr) \
    asm volatile("cp.async.cg.shared.global [%0], [%1], 16;" :: "r"(dst_u32), "l"(src_ptr))
#define CP_COMMIT() asm volatile("cp.async.commit_group;")
#define CP_WAIT0()  asm volatile("cp.async.wait_group 0;" ::: "memory")

// ---------------------------------------------------------------------------
// K0: split w1a into tf32 hi/lo and pack directly in MMA B-fragment order.
//     g_wfrag[((kc*2+ks)*32+ntg)*32+lane] = (bh0,bh1,bl0,bl1) where
//     n = ntg*8 + (lane>>2), k = kc*16 + ks*8 + (lane&3)  (b1 at k+4)
// ---------------------------------------------------------------------------
__global__ void k0_split(const float* __restrict__ w1a)
{
    int w = blockIdx.x * 256 + threadIdx.x;    // 65536
    int lane = w & 31;
    int ntg  = (w >> 5) & 31;
    int ks   = (w >> 10) & 1;
    int kc   = w >> 11;
    int n = ntg * 8 + (lane >> 2);
    int k = kc * 16 + ks * 8 + (lane & 3);
    float w0 = w1a[k * HH + n];
    float w1 = w1a[(k + 4) * HH + n];
    float h0 = tf32_rnd(w0), h1 = tf32_rnd(w1);
    g_wfrag[w] = make_float4(h0, h1, tf32_rnd(w0 - h0), tf32_rnd(w1 - h1));
}

// ---------------------------------------------------------------------------
// K1: pipelined warp-mma tf32 3x-split GEMM. One (i,r) per CTA, 512 threads.
// SMEM: Ab[2][4096] | Bb[2][8192] | red[512] | w2s[256] | b1s[256]  (100 KB)
// A frag layout per stage: ((ks*8+mti)*2+part)*128 + r*32 + gr*4 + (gc^(ks*2+(r>>1)))
// ---------------------------------------------------------------------------
__global__ __launch_bounds__(512, 1)
void k1_mma(const float* __restrict__ obj, const float* __restrict__ geo,
            const float* __restrict__ b1a, const float* __restrict__ w2a)
{
    extern __shared__ float sm[];
    float* Ab  = sm;             // [2][4096]
    float* Bb  = sm + 8192;      // [2][8192]
    float* red = sm + 24576;     // [512]
    float* w2s = red + 512;      // [256]
    float* b1s = w2s + 256;      // [256]

    const int t    = threadIdx.x;
    const int lane = t & 31;
    const int wid  = t >> 5;
    const int mw   = wid & 3;
    const int nw   = wid >> 2;
    const int gr   = lane >> 2;
    const int gc   = lane & 3;

    const int bx = blockIdx.x;   // 0..1023
    const int i  = bx >> 3;
    const int r  = bx & 7;

    const float* obj_r  = obj + (size_t)r * NN * DD;
    const float* obj_i  = obj_r + (size_t)i * DD;
    const float* geo_ri = geo + ((size_t)(r * NN + i) * NN) * DD;

    if (t < 256) { w2s[t] = w2a[t]; b1s[t] = b1a[t]; }

    // A-build per-thread constants: thread builds (j=aj, k=ak..ak+3) of each chunk
    const int aj   = t >> 2;
    const int ak   = (t & 3) << 2;
    const int lr   = aj & 15;
    const int a_mti = aj >> 4;
    const int a_gr  = lr & 7;
    const int a_rh  = lr >> 3;
    const int a_ks  = ak >> 3;
    const int a_kh  = (ak >> 2) & 1;
    const int a_xc  = a_ks * 2 + a_kh;
    const int a_base = ((a_ks * 8 + a_mti) * 2) * 128 + (a_kh * 2 + a_rh) * 32 + a_gr * 4;

    const float* gsrc = geo_ri + (size_t)aj * DD + ak;
    const float* osrc = obj_r  + (size_t)aj * DD + ak;
    const float* isrc = obj_i + ak;

    const uint32_t bsm = (uint32_t)__cvta_generic_to_shared(Bb);

    float c[2][8][4];
#pragma unroll
    for (int mt = 0; mt < 2; mt++)
#pragma unroll
        for (int nt = 0; nt < 8; nt++)
#pragma unroll
            for (int e = 0; e < 4; e++) c[mt][nt][e] = 0.f;

    // ---- prologue: B(0) cp.async; A(0) build+store into stage 0 ----
    {
        const float4* src = g_wfrag + t;
#pragma unroll
        for (int q = 0; q < 4; q++)
            CP_ASYNC16(bsm + (t + q * 512) * 16, src + q * 512);
        CP_COMMIT();
    }
    float4 g4 = *(const float4*)gsrc;
    float4 oj = *(const float4*)osrc;
    float4 oi = *(const float4*)isrc;
    {
        float x0 = fmaf(oi.x, oj.x, g4.x), x1 = fmaf(oi.y, oj.y, g4.y);
        float x2 = fmaf(oi.z, oj.z, g4.z), x3 = fmaf(oi.w, oj.w, g4.w);
        float h0 = tf32_rnd(x0), h1 = tf32_rnd(x1), h2 = tf32_rnd(x2), h3 = tf32_rnd(x3);
        float* dA = Ab;
        dA[a_base + (0 ^ a_xc)] = h0;  dA[a_base + (1 ^ a_xc)] = h1;
        dA[a_base + (2 ^ a_xc)] = h2;  dA[a_base + (3 ^ a_xc)] = h3;
        dA[a_base + 128 + (0 ^ a_xc)] = tf32_rnd(x0 - h0);
        dA[a_base + 128 + (1 ^ a_xc)] = tf32_rnd(x1 - h1);
        dA[a_base + 128 + (2 ^ a_xc)] = tf32_rnd(x2 - h2);
        dA[a_base + 128 + (3 ^ a_xc)] = tf32_rnd(x3 - h3);
    }

    for (int kc = 0; kc < 32; kc++) {
        const int s = kc & 1;
        CP_WAIT0();
        __syncthreads();

        if (kc < 31) {
            // issue B(kc+1) into stage s^1
            const float4* src = g_wfrag + (size_t)(kc + 1) * 2048 + t;
            const uint32_t dst0 = bsm + (s ^ 1) * 32768 + t * 16;
#pragma unroll
            for (int q = 0; q < 4; q++)
                CP_ASYNC16(dst0 + q * 8192, src + q * 512);
            CP_COMMIT();
            // prefetch A source for kc+1
            g4 = *(const float4*)(gsrc + (kc + 1) * 16);
            oj = *(const float4*)(osrc + (kc + 1) * 16);
            oi = *(const float4*)(isrc + (kc + 1) * 16);
        }

        // ---- MMA over chunk kc from stage s ----
        const float* A = Ab + s * 4096;
        const float* B = Bb + s * 8192;
#pragma unroll
        for (int ks = 0; ks < 2; ks++) {
            uint32_t ah[2][4], al[2][4];
#pragma unroll
            for (int mt = 0; mt < 2; mt++) {
                const int blk = ((ks * 8 + (mw * 2 + mt)) * 2) * 128;
#pragma unroll
                for (int rr = 0; rr < 4; rr++) {
                    const int off = blk + rr * 32 + gr * 4 + (gc ^ (ks * 2 + (rr >> 1)));
                    ah[mt][rr] = __float_as_uint(A[off]);
                    al[mt][rr] = __float_as_uint(A[off + 128]);
                }
            }
#pragma unroll
            for (int nt = 0; nt < 8; nt++) {
                float4 bf = *(const float4*)&B[((ks * 32 + nw * 8 + nt) * 32 + lane) * 4];
                const uint32_t bh0 = __float_as_uint(bf.x), bh1 = __float_as_uint(bf.y);
                const uint32_t bl0 = __float_as_uint(bf.z), bl1 = __float_as_uint(bf.w);
#pragma unroll
                for (int mt = 0; mt < 2; mt++) {
                    mma_tf32(c[mt][nt], ah[mt], bh0, bh1);
                    mma_tf32(c[mt][nt], ah[mt], bl0, bl1);
                    mma_tf32(c[mt][nt], al[mt], bh0, bh1);
                }
            }
        }

        if (kc < 31) {
            // split + store A(kc+1) into stage s^1
            float x0 = fmaf(oi.x, oj.x, g4.x), x1 = fmaf(oi.y, oj.y, g4.y);
            float x2 = fmaf(oi.z, oj.z, g4.z), x3 = fmaf(oi.w, oj.w, g4.w);
            float h0 = tf32_rnd(x0), h1 = tf32_rnd(x1), h2 = tf32_rnd(x2), h3 = tf32_rnd(x3);
            float* dA = Ab + (s ^ 1) * 4096;
            dA[a_base + (0 ^ a_xc)] = h0;  dA[a_base + (1 ^ a_xc)] = h1;
            dA[a_base + (2 ^ a_xc)] = h2;  dA[a_base + (3 ^ a_xc)] = h3;
            dA[a_base + 128 + (0 ^ a_xc)] = tf32_rnd(x0 - h0);
            dA[a_base + 128 + (1 ^ a_xc)] = tf32_rnd(x1 - h1);
            dA[a_base + 128 + (2 ^ a_xc)] = tf32_rnd(x2 - h2);
            dA[a_base + 128 + (3 ^ a_xc)] = tf32_rnd(x3 - h3);
        }
    }

    // ---- epilogue: logit[j] = sum_h relu(C + b1a) * w2a, reduce across nw ----
    const int mbase = mw * 32;
    const int nbase = nw * 64;
    float part[2][2] = {{0.f, 0.f}, {0.f, 0.f}};
#pragma unroll
    for (int mt = 0; mt < 2; mt++)
#pragma unroll
        for (int nt = 0; nt < 8; nt++)
#pragma unroll
            for (int rv = 0; rv < 2; rv++)
#pragma unroll
                for (int e = 0; e < 2; e++) {
                    int h = nbase + nt * 8 + gc * 2 + e;
                    float v = c[mt][nt][rv * 2 + e] + b1s[h];
                    part[mt][rv] += fmaxf(v, 0.f) * w2s[h];
                }
    __syncthreads();
#pragma unroll
    for (int mt = 0; mt < 2; mt++)
#pragma unroll
        for (int rv = 0; rv < 2; rv++) {
            float p = part[mt][rv];
            p += __shfl_xor_sync(0xffffffffu, p, 1);
            p += __shfl_xor_sync(0xffffffffu, p, 2);
            if (gc == 0)
                red[nw * 128 + mbase + mt * 16 + rv * 8 + gr] = p;
        }
    __syncthreads();
    if (t < 128)
        g_lacc[(r * NN + i) * NN + t] =
            (red[t] + red[128 + t]) + (red[256 + t] + red[384 + t]);
}

// ---------------------------------------------------------------------------
// K2: mean over r + b2a -> out; probs = sigmoid*mask
// ---------------------------------------------------------------------------
__global__ void k2_finish(const float* __restrict__ mask,
                          const float* __restrict__ b2a,
                          float* __restrict__ out)
{
    int idx = blockIdx.x * 256 + threadIdx.x;
    float s = 0.f;
#pragma unroll
    for (int r = 0; r < RB; r++) s += g_lacc[r * (NN * NN) + idx];
    float v = s * 0.125f + b2a[0];
    out[idx] = v;
    g_probs[idx] = (1.f / (1.f + expf(-v))) * mask[idx];
}

// ---------------------------------------------------------------------------
// K3: tournament top-64. Per-thread best-of-16 + taken mask; 64 reductions.
// ---------------------------------------------------------------------------
__global__ void k3_topk(float* __restrict__ out)
{
    __shared__ float sval[1024];
    __shared__ int   sidx[1024];
    __shared__ float wv[32];
    __shared__ int   wi[32];
    __shared__ int   winner;
    const int t = threadIdx.x;
    const int base = t * 16;

    unsigned taken = 0;
    {
        float bv = -1e30f; int bi = 0x7fffffff;
#pragma unroll
        for (int u = 0; u < 16; u++) {
            float v = g_probs[base + u];
            if (v > bv) { bv = v; bi = base + u; }
        }
        sval[t] = bv; sidx[t] = bi;
    }
    __syncthreads();

    for (int it = 0; it < KK; it++) {
        float v = sval[t]; int ix = sidx[t];
#pragma unroll
        for (int off = 16; off; off >>= 1) {
            float ov = __shfl_down_sync(0xffffffffu, v, off);
            int   oi = __shfl_down_sync(0xffffffffu, ix, off);
            if (ov > v || (ov == v && oi < ix)) { v = ov; ix = oi; }
        }
        if ((t & 31) == 0) { wv[t >> 5] = v; wi[t >> 5] = ix; }
        __syncthreads();
        if (t < 32) {
            v = wv[t]; ix = wi[t];
#pragma unroll
            for (int off = 16; off; off >>= 1) {
                float ov = __shfl_down_sync(0xffffffffu, v, off);
                int   oi = __shfl_down_sync(0xffffffffu, ix, off);
                if (ov > v || (ov == v && oi < ix)) { v = ov; ix = oi; }
            }
            if (t == 0) {
                winner = ix;
                g_topk[it] = ix;
                out[NN * NN + KK * KK + it] = (float)ix;
            }
        }
        __syncthreads();
        const int win = winner;
        if ((win >> 4) == t) {
            taken |= 1u << (win & 15);
            float nb = -1e30f; int ni = 0x7fffffff;
#pragma unroll
            for (int u = 0; u < 16; u++) {
                if (!((taken >> u) & 1)) {
                    float v2 = g_probs[base + u];
                    if (v2 > nb) { nb = v2; ni = base + u; }
                }
            }
            sval[t] = nb; sidx[t] = ni;
        }
        __syncthreads();
    }
}

// ---------------------------------------------------------------------------
// K4: gather averaged pair features at top-k pairs
// ---------------------------------------------------------------------------
__global__ void k4_pf(const float* __restrict__ obj, const float* __restrict__ geo)
{
    int p = blockIdx.x;
    int t = threadIdx.x;
    int ind = g_topk[p];
    int i = ind >> 7;
    int j = ind & 127;
    int d = t * 4;

    float4 s = make_float4(0.f, 0.f, 0.f, 0.f);
#pragma unroll
    for (int r = 0; r < RB; r++) {
        float4 oi = *(const float4*)(obj + (size_t)(r * NN + i) * DD + d);
        float4 oj = *(const float4*)(obj + (size_t)(r * NN + j) * DD + d);
        float4 g  = *(const float4*)(geo + (size_t)((r * NN + i) * NN + j) * DD + d);
        s.x += fmaf(oi.x, oj.x, g.x);
        s.y += fmaf(oi.y, oj.y, g.y);
        s.z += fmaf(oi.z, oj.z, g.z);
        s.w += fmaf(oi.w, oj.w, g.w);
    }
    s.x *= 0.125f; s.y *= 0.125f; s.z *= 0.125f; s.w *= 0.125f;
    *(float4*)(g_pf + p * DD + d) = s;
}

// ---------------------------------------------------------------------------
// K5: p2p scorer (fp32, small)
// ---------------------------------------------------------------------------
__global__ __launch_bounds__(256, 2)
void k5_p2p(const float* __restrict__ w1b, const float* __restrict__ b1b,
            const float* __restrict__ w2b, const float* __restrict__ b2b,
            float* __restrict__ out)
{
    __shared__ float As2[16][17];
    __shared__ float Bs2[16][256];

    int t = threadIdx.x;
    int b = blockIdx.x;
    int row0   = b * 16;
    int i2     = row0 >> 6;
    int j2base = row0 & 63;
    int rowl = t >> 4;
    int hg   = t & 15;

    const float* pfi = g_pf + i2 * DD;
    float acc[16];
#pragma unroll
    for (int hh = 0; hh < 16; hh++) acc[hh] = 0.f;

    for (int d0 = 0; d0 < DD; d0 += 16) {
        {
            int rl = t >> 4, k = t & 15;
            As2[k][rl] = pfi[d0 + k] * g_pf[(j2base + rl) * DD + d0 + k];
        }
#pragma unroll
        for (int l = 0; l < 4; l++) {
            int q  = t + l * 256;
            int k  = q >> 6;
            int h4 = (q & 63) << 2;
            *(float4*)&Bs2[k][h4] = *(const float4*)(w1b + (d0 + k) * HH + h4);
        }
        __syncthreads();
#pragma unroll 4
        for (int k = 0; k < 16; k++) {
            float a = As2[k][rowl];
            float bv[16];
            *(float4*)&bv[0]  = *(const float4*)&Bs2[k][hg * 16];
            *(float4*)&bv[4]  = *(const float4*)&Bs2[k][hg * 16 + 4];
            *(float4*)&bv[8]  = *(const float4*)&Bs2[k][hg * 16 + 8];
            *(float4*)&bv[12] = *(const float4*)&Bs2[k][hg * 16 + 12];
#pragma unroll
            for (int hh = 0; hh < 16; hh++)
                acc[hh] = fmaf(a, bv[hh], acc[hh]);
        }
        __syncthreads();
    }

    float p = 0.f;
#pragma unroll
    for (int hh = 0; hh < 16; hh++) {
        int h = hg * 16 + hh;
        p += fmaxf(acc[hh] + b1b[h], 0.f) * w2b[h];
    }
#pragma unroll
    for (int off = 8; off; off >>= 1)
        p += __shfl_xor_sync(0xffffffffu, p, off);
    if (hg == 0)
        out[NN * NN + row0 + rowl] = p + b2b[0];
}

// ---------------------------------------------------------------------------
extern "C" void kernel_launch(void* const* d_in, const int* in_sizes, int n_in,
                              void* d_out, int out_size)
{
    const float* obj  = (const float*)d_in[0];
    const float* geo  = (const float*)d_in[1];
    const float* mask = (const float*)d_in[2];
    const float* w1a  = (const float*)d_in[3];
    const float* b1a  = (const float*)d_in[4];
    const float* w2a  = (const float*)d_in[5];
    const float* b2a  = (const float*)d_in[6];
    const float* w1b  = (const float*)d_in[7];
    const float* b1b  = (const float*)d_in[8];
    const float* w2b  = (const float*)d_in[9];
    const float* b2b  = (const float*)d_in[10];
    float* out = (float*)d_out;

    const int smem_k1 = 25600 * 4;   // 102400 B
    cudaFuncSetAttribute(k1_mma, cudaFuncAttributeMaxDynamicSharedMemorySize, smem_k1);

    k0_split<<<256, 256>>>(w1a);
    k1_mma<<<NN * RB, 512, smem_k1>>>(obj, geo, b1a, w2a);
    k2_finish<<<64, 256>>>(mask, b2a, out);
    k3_topk<<<1, 1024>>>(out);
    k4_pf<<<KK, 128>>>(obj, geo);
    k5_p2p<<<256, 256>>>(w1b, b1b, w2b, b2b, out);
}

// round 5
// speedup vs baseline: 2.3654x; 1.2743x over previous
#include <cuda_runtime.h>
#include <cuda_fp16.h>
#include <cstdint>
#include <math.h>

#define RB 8
#define NN 128
#define DD 512
#define HH 256
#define KK 64

// ---------------------------------------------------------------------------
// Scratch (__device__ globals; no allocation allowed)
// ---------------------------------------------------------------------------
__device__ float g_lacc[RB * NN * NN];
__device__ float g_probs[NN * NN];
__device__ int   g_topk[KK];
__device__ float g_pf[KK * DD];
__device__ uint4 g_wfragH[32 * 32 * 32];  // [kc][ntg][lane] = (bh0,bh1,bl0,bl1) half2 quads

__device__ __forceinline__ uint32_t h2u(half2 h) {
    return *reinterpret_cast<uint32_t*>(&h);
}

__device__ __forceinline__ void mma_f16(float* c, const uint32_t* a, uint32_t b0, uint32_t b1) {
    asm volatile(
        "mma.sync.aligned.m16n8k16.row.col.f32.f16.f16.f32 "
        "{%0,%1,%2,%3}, {%4,%5,%6,%7}, {%8,%9}, {%0,%1,%2,%3};"
        : "+f"(c[0]), "+f"(c[1]), "+f"(c[2]), "+f"(c[3])
        : "r"(a[0]), "r"(a[1]), "r"(a[2]), "r"(a[3]), "r"(b0), "r"(b1));
}

#define CP_ASYNC16(dst_u32, src_ptr) \
    asm volatile("cp.async.cg.shared.global [%0], [%1], 16;" :: "r"(dst_u32), "l"(src_ptr))
#define CP_COMMIT() asm volatile("cp.async.commit_group;")
#define CP_WAIT0()  asm volatile("cp.async.wait_group 0;" ::: "memory")

// ---------------------------------------------------------------------------
// K0: pack w1a (scaled x16) into fp16 hi/lo MMA B-fragment quads.
//     quad(kc,ntg,lane): n = ntg*8+(lane>>2); k = kc*16 + {2gc,2gc+1,2gc+8,2gc+9}
// ---------------------------------------------------------------------------
__global__ void k0_pack(const float* __restrict__ w1a)
{
    int w = blockIdx.x * 256 + threadIdx.x;     // 32768
    int lane = w & 31, ntg = (w >> 5) & 31, kc = w >> 10;
    int n = ntg * 8 + (lane >> 2), gc = lane & 3, k0 = kc * 16;
    const float S = 16.f;
    float a0 = w1a[(k0 + 2 * gc) * HH + n] * S;
    float a1 = w1a[(k0 + 2 * gc + 1) * HH + n] * S;
    float a2 = w1a[(k0 + 2 * gc + 8) * HH + n] * S;
    float a3 = w1a[(k0 + 2 * gc + 9) * HH + n] * S;
    half2 h0 = __floats2half2_rn(a0, a1), h1 = __floats2half2_rn(a2, a3);
    half2 l0 = __floats2half2_rn(a0 - __low2float(h0), a1 - __high2float(h0));
    half2 l1 = __floats2half2_rn(a2 - __low2float(h1), a3 - __high2float(h1));
    g_wfragH[w] = make_uint4(h2u(h0), h2u(h1), h2u(l0), h2u(l1));
}

// ---------------------------------------------------------------------------
// K1: fp16 3x-split warp-mma GEMM. One (i,r) per CTA, 512 threads (16 warps).
//     k-chunks of 16; A sources (geo/obj) cp.async double-buffered; A frags
//     built in registers; B quads LDS.128. Warp (mw,nw): rows mw*32, cols nw*64.
// SMEM floats: Gb[2][2048] | Ob[2][2048] | Bq[2][4096] | Oi[2][16] | red[512] | w2s[256] | b1s[256]
// ---------------------------------------------------------------------------
__global__ __launch_bounds__(512, 1)
void k1_mma(const float* __restrict__ obj, const float* __restrict__ geo,
            const float* __restrict__ b1a, const float* __restrict__ w2a)
{
    extern __shared__ float sm[];
    float* Gb  = sm;                 // [2][2048]
    float* Ob  = sm + 4096;          // [2][2048]
    float* Bq  = sm + 8192;          // [2][4096]
    float* OiS = sm + 16384;         // [2][16]
    float* red = sm + 16416;         // [512]
    float* w2s = red + 512;          // [256]
    float* b1s = w2s + 256;          // [256]

    const int t    = threadIdx.x;
    const int lane = t & 31;
    const int wid  = t >> 5;
    const int mw   = wid & 3;
    const int nw   = wid >> 2;
    const int gr   = lane >> 2;
    const int gc   = lane & 3;
    const int mbase = mw * 32;

    const int bx = blockIdx.x;       // 0..1023
    const int i  = bx >> 3;
    const int r  = bx & 7;

    const float* obj_r  = obj + (size_t)r * NN * DD;
    const float* obj_i  = obj_r + (size_t)i * DD;
    const float* geo_ri = geo + ((size_t)(r * NN + i) * NN) * DD;

    if (t < 256) { w2s[t] = w2a[t]; b1s[t] = b1a[t]; }

    // per-thread copy-role constants
    const int crow = t >> 2;                              // 0..127
    const int cgq  = t & 3;                               // granule 0..3
    const int gsw  = ((cgq ^ (crow & 3)) << 2);           // swizzled granule (floats)
    const int adst = crow * 16 + gsw;                     // A-side smem float offset
    const float* gsrc0 = geo_ri + (size_t)crow * DD + cgq * 4;
    const float* osrc0 = obj_r  + (size_t)crow * DD + cgq * 4;
    const uint32_t sbase = (uint32_t)__cvta_generic_to_shared(sm);

    float c[2][8][4];
#pragma unroll
    for (int mt = 0; mt < 2; mt++)
#pragma unroll
        for (int nt = 0; nt < 8; nt++)
#pragma unroll
            for (int e = 0; e < 4; e++) c[mt][nt][e] = 0.f;

    // ---- prologue: stage 0 copies for chunk 0 ----
    {
        CP_ASYNC16(sbase + (0 + adst) * 4, gsrc0);
        CP_ASYNC16(sbase + (4096 + adst) * 4, osrc0);
        CP_ASYNC16(sbase + (8192 + t * 4) * 4, g_wfragH + t);
        CP_ASYNC16(sbase + (8192 + (t + 512) * 4) * 4, g_wfragH + t + 512);
        if (t < 4) CP_ASYNC16(sbase + (16384 + t * 4) * 4, obj_i + t * 4);
        CP_COMMIT();
    }

    for (int kc = 0; kc < 32; kc++) {
        const int s = kc & 1;
        CP_WAIT0();
        __syncthreads();

        if (kc < 31) {
            const int s1 = s ^ 1;
            const int kf = (kc + 1) * 16;
            CP_ASYNC16(sbase + (s1 * 2048 + adst) * 4, gsrc0 + kf);
            CP_ASYNC16(sbase + (4096 + s1 * 2048 + adst) * 4, osrc0 + kf);
            const uint4* bsrc = g_wfragH + (size_t)(kc + 1) * 1024;
            CP_ASYNC16(sbase + (8192 + s1 * 4096 + t * 4) * 4, bsrc + t);
            CP_ASYNC16(sbase + (8192 + s1 * 4096 + (t + 512) * 4) * 4, bsrc + t + 512);
            if (t < 4) CP_ASYNC16(sbase + (16384 + s1 * 16 + t * 4) * 4, obj_i + kf + t * 4);
            CP_COMMIT();
        }

        // ---- build A fragments (hi/lo) in registers ----
        const float* G  = Gb + s * 2048;
        const float* O  = Ob + s * 2048;
        const float* Oi = OiS + s * 16;
        float2 oiv[2];
        oiv[0] = *(const float2*)(Oi + 2 * gc);
        oiv[1] = *(const float2*)(Oi + 8 + 2 * gc);

        uint32_t ah[2][4], al[2][4];
#pragma unroll
        for (int mt = 0; mt < 2; mt++)
#pragma unroll
            for (int rh = 0; rh < 2; rh++) {
                const int rr = mbase + mt * 16 + rh * 8 + gr;
                const int rb = rr * 16, ra = rr & 3;
#pragma unroll
                for (int kp = 0; kp < 2; kp++) {
                    const int ad = rb + (((kp * 2 + (gc >> 1)) ^ ra) << 2) + 2 * (gc & 1);
                    float2 gx = *(const float2*)(G + ad);
                    float2 ox = *(const float2*)(O + ad);
                    float X0 = fmaf(oiv[kp].x, ox.x, gx.x);
                    float X1 = fmaf(oiv[kp].y, ox.y, gx.y);
                    half2 h = __floats2half2_rn(X0, X1);
                    float l0 = X0 - __low2float(h);
                    float l1 = X1 - __high2float(h);
                    half2 l = __floats2half2_rn(l0, l1);
                    ah[mt][rh + 2 * kp] = h2u(h);
                    al[mt][rh + 2 * kp] = h2u(l);
                }
            }

        // ---- MMAs: 8 nt x 2 mt x 3 passes ----
        const float* Bs = Bq + s * 4096;
#pragma unroll
        for (int nt = 0; nt < 8; nt++) {
            const uint4 bq = *(const uint4*)(Bs + ((nw * 8 + nt) * 32 + lane) * 4);
#pragma unroll
            for (int mt = 0; mt < 2; mt++) {
                mma_f16(c[mt][nt], ah[mt], bq.x, bq.y);
                mma_f16(c[mt][nt], ah[mt], bq.z, bq.w);
                mma_f16(c[mt][nt], al[mt], bq.x, bq.y);
            }
        }
    }

    // ---- epilogue: logit[j] = sum_h relu(C/16 + b1a) * w2a, reduce across nw ----
    float part[2][2] = {{0.f, 0.f}, {0.f, 0.f}};
#pragma unroll
    for (int mt = 0; mt < 2; mt++)
#pragma unroll
        for (int nt = 0; nt < 8; nt++)
#pragma unroll
            for (int rv = 0; rv < 2; rv++)
#pragma unroll
                for (int e = 0; e < 2; e++) {
                    int h = nw * 64 + nt * 8 + gc * 2 + e;
                    float v = c[mt][nt][rv * 2 + e] * 0.0625f + b1s[h];
                    part[mt][rv] += fmaxf(v, 0.f) * w2s[h];
                }
    __syncthreads();
#pragma unroll
    for (int mt = 0; mt < 2; mt++)
#pragma unroll
        for (int rv = 0; rv < 2; rv++) {
            float p = part[mt][rv];
            p += __shfl_xor_sync(0xffffffffu, p, 1);
            p += __shfl_xor_sync(0xffffffffu, p, 2);
            if (gc == 0)
                red[nw * 128 + mbase + mt * 16 + rv * 8 + gr] = p;
        }
    __syncthreads();
    if (t < 128)
        g_lacc[(r * NN + i) * NN + t] =
            (red[t] + red[128 + t]) + (red[256 + t] + red[384 + t]);
}

// ---------------------------------------------------------------------------
// K2: mean over r + b2a -> out; probs = sigmoid*mask
// ---------------------------------------------------------------------------
__global__ void k2_finish(const float* __restrict__ mask,
                          const float* __restrict__ b2a,
                          float* __restrict__ out)
{
    int idx = blockIdx.x * 256 + threadIdx.x;
    float s = 0.f;
#pragma unroll
    for (int r = 0; r < RB; r++) s += g_lacc[r * (NN * NN) + idx];
    float v = s * 0.125f + b2a[0];
    out[idx] = v;
    g_probs[idx] = (1.f / (1.f + expf(-v))) * mask[idx];
}

// ---------------------------------------------------------------------------
// K3: top-64, 256 threads x 64 elems, per-thread sorted top-4 register cache.
// ---------------------------------------------------------------------------
__global__ void k3_topk(float* __restrict__ out)
{
    __shared__ float wv[8];
    __shared__ int   wi[8];
    __shared__ int   bw_i;
    const int t = threadIdx.x;
    const int base = t * 64;

    float v0 = -1e30f, v1 = -1e30f, v2 = -1e30f, v3 = -1e30f;
    int   i0 = 0x7fffffff, i1 = 0x7fffffff, i2 = 0x7fffffff, i3 = 0x7fffffff;
#pragma unroll 4
    for (int u = 0; u < 64; u++) {
        float v = g_probs[base + u];
        int ix = base + u;
        if (v > v3) {
            if (v > v2) {
                v3 = v2; i3 = i2;
                if (v > v1) {
                    v2 = v1; i2 = i1;
                    if (v > v0) { v1 = v0; i1 = i0; v0 = v; i0 = ix; }
                    else        { v1 = v;  i1 = ix; }
                } else { v2 = v; i2 = ix; }
            } else { v3 = v; i3 = ix; }
        }
    }
    int cnt = 4;
    unsigned long long taken = 0ull;

    for (int it = 0; it < KK; it++) {
        float v = v0; int ix = i0;
#pragma unroll
        for (int off = 16; off; off >>= 1) {
            float ov = __shfl_down_sync(0xffffffffu, v, off);
            int   oi = __shfl_down_sync(0xffffffffu, ix, off);
            if (ov > v || (ov == v && oi < ix)) { v = ov; ix = oi; }
        }
        if ((t & 31) == 0) { wv[t >> 5] = v; wi[t >> 5] = ix; }
        __syncthreads();
        if (t < 32) {
            v  = (t < 8) ? wv[t] : -1e30f;
            ix = (t < 8) ? wi[t] : 0x7fffffff;
#pragma unroll
            for (int off = 4; off; off >>= 1) {
                float ov = __shfl_down_sync(0xffffffffu, v, off);
                int   oi = __shfl_down_sync(0xffffffffu, ix, off);
                if (ov > v || (ov == v && oi < ix)) { v = ov; ix = oi; }
            }
            if (t == 0) {
                bw_i = ix;
                g_topk[it] = ix;
                out[NN * NN + KK * KK + it] = (float)ix;
            }
        }
        __syncthreads();
        const int win = bw_i;
        if ((win >> 6) == t) {
            taken |= 1ull << (win & 63);
            v0 = v1; i0 = i1; v1 = v2; i1 = i2; v2 = v3; i2 = i3;
            v3 = -1e30f; i3 = 0x7fffffff;
            if (--cnt == 0) {
                v0 = v1 = v2 = v3 = -1e30f;
                i0 = i1 = i2 = i3 = 0x7fffffff;
                for (int u = 0; u < 64; u++) {
                    if ((taken >> u) & 1ull) continue;
                    float vv = g_probs[base + u];
                    int iu = base + u;
                    if (vv > v3) {
                        if (vv > v2) {
                            v3 = v2; i3 = i2;
                            if (vv > v1) {
                                v2 = v1; i2 = i1;
                                if (vv > v0) { v1 = v0; i1 = i0; v0 = vv; i0 = iu; }
                                else          { v1 = vv; i1 = iu; }
                            } else { v2 = vv; i2 = iu; }
                        } else { v3 = vv; i3 = iu; }
                    }
                }
                cnt = 4;
            }
        }
        __syncthreads();
    }
}

// ---------------------------------------------------------------------------
// K4: gather averaged pair features at top-k pairs
// ---------------------------------------------------------------------------
__global__ void k4_pf(const float* __restrict__ obj, const float* __restrict__ geo)
{
    int p = blockIdx.x;
    int t = threadIdx.x;
    int ind = g_topk[p];
    int i = ind >> 7;
    int j = ind & 127;
    int d = t * 4;

    float4 s = make_float4(0.f, 0.f, 0.f, 0.f);
#pragma unroll
    for (int r = 0; r < RB; r++) {
        float4 oi = *(const float4*)(obj + (size_t)(r * NN + i) * DD + d);
        float4 oj = *(const float4*)(obj + (size_t)(r * NN + j) * DD + d);
        float4 g  = *(const float4*)(geo + (size_t)((r * NN + i) * NN + j) * DD + d);
        s.x += fmaf(oi.x, oj.x, g.x);
        s.y += fmaf(oi.y, oj.y, g.y);
        s.z += fmaf(oi.z, oj.z, g.z);
        s.w += fmaf(oi.w, oj.w, g.w);
    }
    s.x *= 0.125f; s.y *= 0.125f; s.z *= 0.125f; s.w *= 0.125f;
    *(float4*)(g_pf + p * DD + d) = s;
}

// ---------------------------------------------------------------------------
// K5: p2p scorer (fp32, small)
// ---------------------------------------------------------------------------
__global__ __launch_bounds__(256, 2)
void k5_p2p(const float* __restrict__ w1b, const float* __restrict__ b1b,
            const float* __restrict__ w2b, const float* __restrict__ b2b,
            float* __restrict__ out)
{
    __shared__ float As2[16][17];
    __shared__ float Bs2[16][256];

    int t = threadIdx.x;
    int b = blockIdx.x;
    int row0   = b * 16;
    int i2     = row0 >> 6;
    int j2base = row0 & 63;
    int rowl = t >> 4;
    int hg   = t & 15;

    const float* pfi = g_pf + i2 * DD;
    float acc[16];
#pragma unroll
    for (int hh = 0; hh < 16; hh++) acc[hh] = 0.f;

    for (int d0 = 0; d0 < DD; d0 += 16) {
        {
            int rl = t >> 4, k = t & 15;
            As2[k][rl] = pfi[d0 + k] * g_pf[(j2base + rl) * DD + d0 + k];
        }
#pragma unroll
        for (int l = 0; l < 4; l++) {
            int q  = t + l * 256;
            int k  = q >> 6;
            int h4 = (q & 63) << 2;
            *(float4*)&Bs2[k][h4] = *(const float4*)(w1b + (d0 + k) * HH + h4);
        }
        __syncthreads();
#pragma unroll 4
        for (int k = 0; k < 16; k++) {
            float a = As2[k][rowl];
            float bv[16];
            *(float4*)&bv[0]  = *(const float4*)&Bs2[k][hg * 16];
            *(float4*)&bv[4]  = *(const float4*)&Bs2[k][hg * 16 + 4];
            *(float4*)&bv[8]  = *(const float4*)&Bs2[k][hg * 16 + 8];
            *(float4*)&bv[12] = *(const float4*)&Bs2[k][hg * 16 + 12];
#pragma unroll
            for (int hh = 0; hh < 16; hh++)
                acc[hh] = fmaf(a, bv[hh], acc[hh]);
        }
        __syncthreads();
    }

    float p = 0.f;
#pragma unroll
    for (int hh = 0; hh < 16; hh++) {
        int h = hg * 16 + hh;
        p += fmaxf(acc[hh] + b1b[h], 0.f) * w2b[h];
    }
#pragma unroll
    for (int off = 8; off; off >>= 1)
        p += __shfl_xor_sync(0xffffffffu, p, off);
    if (hg == 0)
        out[NN * NN + row0 + rowl] = p + b2b[0];
}

// ---------------------------------------------------------------------------
extern "C" void kernel_launch(void* const* d_in, const int* in_sizes, int n_in,
                              void* d_out, int out_size)
{
    const float* obj  = (const float*)d_in[0];
    const float* geo  = (const float*)d_in[1];
    const float* mask = (const float*)d_in[2];
    const float* w1a  = (const float*)d_in[3];
    const float* b1a  = (const float*)d_in[4];
    const float* w2a  = (const float*)d_in[5];
    const float* b2a  = (const float*)d_in[6];
    const float* w1b  = (const float*)d_in[7];
    const float* b1b  = (const float*)d_in[8];
    const float* w2b  = (const float*)d_in[9];
    const float* b2b  = (const float*)d_in[10];
    float* out = (float*)d_out;

    const int smem_k1 = 17440 * 4;   // 69760 B
    cudaFuncSetAttribute(k1_mma, cudaFuncAttributeMaxDynamicSharedMemorySize, smem_k1);

    k0_pack<<<128, 256>>>(w1a);
    k1_mma<<<NN * RB, 512, smem_k1>>>(obj, geo, b1a, w2a);
    k2_finish<<<64, 256>>>(mask, b2a, out);
    k3_topk<<<1, 256>>>(out);
    k4_pf<<<KK, 128>>>(obj, geo);
    k5_p2p<<<256, 256>>>(w1b, b1b, w2b, b2b, out);
}